// round 12
// baseline (speedup 1.0000x reference)
#include <cuda_runtime.h>
#include <cstdint>
#include <cstddef>

// Problem shape (fixed by setup_inputs)
#define B_DIM 8192
#define D_DIM 4096
#define H_DIM 8192
#define C_DIM 1000
#define C_PAD 1024

// ACL arm_gemm GemmHybrid fp32 K-blocking (verified PASS): KC = 512.
#define KC 512
#define BK 16
#define KC_TILES (KC / BK)   // fold period in BK=16 tiles
#define NTHREADS 512

typedef unsigned long long u64;

// ---- packed dual-fp32 FMA (sm_100+): per-lane IEEE RN fp32 FMA -------------
__device__ __forceinline__ u64 pack2(float lo, float hi) {
    u64 r;
    asm("mov.b64 %0, {%1, %2};" : "=l"(r) : "f"(lo), "f"(hi));
    return r;
}
__device__ __forceinline__ void unpack2(u64 v, float& lo, float& hi) {
    asm("mov.b64 {%0, %1}, %2;" : "=f"(lo), "=f"(hi) : "l"(v));
}
__device__ __forceinline__ void fma2(u64& d, u64 a, u64 b, u64 c) {
    asm("fma.rn.f32x2 %0, %1, %2, %3;" : "=l"(d) : "l"(a), "l"(b), "l"(c));
}

// ---------------- scratch (static device arrays; no runtime allocation) ----
__device__ float g_w1q[(size_t)H_DIM * D_DIM];   // 128 MB  fl(q*scale) weights
__device__ float g_w2q[(size_t)H_DIM * H_DIM];   // 256 MB
__device__ float g_w3q[(size_t)H_DIM * H_DIM];   // 256 MB
__device__ float g_w4q[(size_t)C_PAD * H_DIM];   //  32 MB (rows 1000..1023 zero)
__device__ float g_h1 [(size_t)B_DIM * H_DIM];   // 256 MB (float activations)
__device__ float g_h2 [(size_t)B_DIM * H_DIM];   // 256 MB
__device__ unsigned g_absmax[4];

// ---------------- prologue: zero + fused absmax + fused quant --------------
__global__ void k_zero_absmax() {
    if (threadIdx.x < 4) g_absmax[threadIdx.x] = 0u;
}

__device__ __forceinline__ void absmax_range(const float* __restrict__ w,
                                             size_t n, int idx,
                                             int rb, int nb) {
    __shared__ unsigned sm[256];
    unsigned m = 0u;
    size_t stride = (size_t)nb * 256;
    for (size_t i = (size_t)rb * 256 + threadIdx.x; i < n; i += stride) {
        unsigned b = __float_as_uint(fabsf(w[i]));  // abs-float bit order == value order
        m = m > b ? m : b;
    }
    sm[threadIdx.x] = m;
    __syncthreads();
    for (int s = 128; s > 0; s >>= 1) {
        if (threadIdx.x < (unsigned)s) {
            unsigned o = sm[threadIdx.x + s];
            if (o > sm[threadIdx.x]) sm[threadIdx.x] = o;
        }
        __syncthreads();
    }
    if (threadIdx.x == 0) atomicMax(&g_absmax[idx], sm[0]);
}

__global__ void __launch_bounds__(256) k_absmax_all(const float* __restrict__ w1,
                                                    const float* __restrict__ w2,
                                                    const float* __restrict__ w3,
                                                    const float* __restrict__ w4) {
    int b = blockIdx.x;
    if (b < 1024)      absmax_range(w1, (size_t)H_DIM * D_DIM, 0, b,        1024);
    else if (b < 2560) absmax_range(w2, (size_t)H_DIM * H_DIM, 1, b - 1024, 1536);
    else if (b < 4096) absmax_range(w3, (size_t)H_DIM * H_DIM, 2, b - 2560, 1536);
    else               absmax_range(w4, (size_t)C_DIM * H_DIM, 3, b - 4096, 256);
}

// fl(round(clip(w/s,-3,3)) * s) — IEEE RN div/mul, rintf = half-even = jnp.round
__device__ __forceinline__ void quant_range(const float* __restrict__ w,
                                            float* __restrict__ q,
                                            size_t n_real, size_t n_total,
                                            int idx, int rb, int nb) {
    float scale = __fdiv_rn(__uint_as_float(g_absmax[idx]), 3.0f);
    size_t stride = (size_t)nb * 256;
    for (size_t i = (size_t)rb * 256 + threadIdx.x; i < n_total; i += stride) {
        float v = 0.0f;
        if (i < n_real) {
            float t = __fdiv_rn(w[i], scale);
            t = fminf(fmaxf(t, -3.0f), 3.0f);
            v = __fmul_rn(rintf(t), scale);
        }
        q[i] = v;
    }
}

__global__ void __launch_bounds__(256) k_quant_all(const float* __restrict__ w1,
                                                   const float* __restrict__ w2,
                                                   const float* __restrict__ w3,
                                                   const float* __restrict__ w4,
                                                   float* q1, float* q2,
                                                   float* q3, float* q4) {
    int b = blockIdx.x;
    size_t n1 = (size_t)H_DIM * D_DIM, n2 = (size_t)H_DIM * H_DIM;
    if (b < 2048)      quant_range(w1, q1, n1, n1, 0, b,        2048);
    else if (b < 5120) quant_range(w2, q2, n2, n2, 1, b - 2048, 3072);
    else if (b < 8192) quant_range(w3, q3, n2, n2, 2, b - 5120, 3072);
    else               quant_range(w4, q4, (size_t)C_DIM * H_DIM,
                                   (size_t)C_PAD * H_DIM, 3, b - 8192, 512);
}

// ---------------- ACL-hybrid-order GEMM, 512-thread FFMA2 engine ------------
// Numerics contract (verified PASS): per output element, K split into KC=512
// panels; within a panel a serial ascending fp32 FMA chain from 0; panels
// folded sequentially with one fp32 add each. FFMA2 lanes are independent
// per-element chains (pair over adjacent j) — bit-identical to scalar FFMA.
// 512 threads/CTA, per-thread tile 4x8 -> 32 acc regs -> 16 warps/SM.
template <int EPI>
__global__ void __launch_bounds__(NTHREADS) k_gemm(const float* __restrict__ A,
                                                   const float* __restrict__ Bw,
                                                   int K,
                                                   float* __restrict__ outF,
                                                   const float* __restrict__ bns,
                                                   const float* __restrict__ bnb,
                                                   const float* __restrict__ act_s) {
    extern __shared__ float smdyn[];
    float (*As)[128] = reinterpret_cast<float(*)[128]>(smdyn);              // [BK][128]
    float (*Bs)[128] = reinterpret_cast<float(*)[128]>(smdyn + BK * 128);   // [BK][128]
    float* Csm       = smdyn + 2 * BK * 128;                                // [32][512]

    int bn0 = blockIdx.x * 128;
    int bm0 = blockIdx.y * 128;
    int tid = threadIdx.x;
    int tn = (tid & 15) << 3;   // 0,8,..,120  (8 cols per thread)
    int tm = (tid >> 4) << 2;   // 0,4,..,124  (4 rows per thread)

    u64 acc2[4][4];             // acc2[i][j2] = (acc[i][2j2], acc[i][2j2+1])
#pragma unroll
    for (int i = 0; i < 4; i++)
#pragma unroll
        for (int j2 = 0; j2 < 4; j2++) acc2[i][j2] = 0ull;
#pragma unroll
    for (int e = 0; e < 32; e++) Csm[e * NTHREADS + tid] = 0.0f;

    int lr = tid >> 2;          // 0..127 (row within tile)
    int lc = (tid & 3) << 2;    // 0,4,8,12 (col within BK=16 K slab)

    const float4* ga = reinterpret_cast<const float4*>(
        A + (size_t)(bm0 + lr) * K + lc);
    const float4* gb = reinterpret_cast<const float4*>(
        Bw + (size_t)(bn0 + lr) * K + lc);

    // ---- load tile 0 ----
    float4 pa = ga[0];
    float4 pb = gb[0];

    int nt = K / BK;
    for (int t = 0; t < nt; t++) {
        // store current tile to smem
        As[lc + 0][lr] = pa.x; As[lc + 1][lr] = pa.y;
        As[lc + 2][lr] = pa.z; As[lc + 3][lr] = pa.w;
        Bs[lc + 0][lr] = pb.x; Bs[lc + 1][lr] = pb.y;
        Bs[lc + 2][lr] = pb.z; Bs[lc + 3][lr] = pb.w;
        __syncthreads();

        // prefetch next tile into registers (hides DRAM/L2 latency)
        if (t + 1 < nt) {
            pa = ga[(size_t)(t + 1) * (BK >> 2)];
            pb = gb[(size_t)(t + 1) * (BK >> 2)];
        }

#pragma unroll
        for (int k = 0; k < BK; k++) {   // ascending k: serial dependent FMA chain
            float a[4], b[8];
            *reinterpret_cast<float4*>(a)     = *reinterpret_cast<const float4*>(&As[k][tm]);
            *reinterpret_cast<float4*>(b)     = *reinterpret_cast<const float4*>(&Bs[k][tn]);
            *reinterpret_cast<float4*>(b + 4) = *reinterpret_cast<const float4*>(&Bs[k][tn + 4]);
            // b pairs: adjacent registers of the aligned v4 quads — no packing
            u64 b2[4];
            b2[0] = *reinterpret_cast<const u64*>(&b[0]);
            b2[1] = *reinterpret_cast<const u64*>(&b[2]);
            b2[2] = *reinterpret_cast<const u64*>(&b[4]);
            b2[3] = *reinterpret_cast<const u64*>(&b[6]);
#pragma unroll
            for (int i = 0; i < 4; i++) {
                u64 a2 = pack2(a[i], a[i]);
#pragma unroll
                for (int j2 = 0; j2 < 4; j2++)
                    fma2(acc2[i][j2], a2, b2[j2], acc2[i][j2]);
            }
        }
        __syncthreads();
        if (((t + 1) % KC_TILES) == 0) {   // panel boundary: fold partial into C
#pragma unroll
            for (int i = 0; i < 4; i++)
#pragma unroll
                for (int j2 = 0; j2 < 4; j2++) {
                    float lo, hi;
                    unpack2(acc2[i][j2], lo, hi);
                    int e = i * 8 + j2 * 2;
                    Csm[e * NTHREADS + tid] =
                        __fadd_rn(Csm[e * NTHREADS + tid], lo);
                    Csm[(e + 1) * NTHREADS + tid] =
                        __fadd_rn(Csm[(e + 1) * NTHREADS + tid], hi);
                    acc2[i][j2] = 0ull;
                }
        }
    }
    // final (possibly partial) panel fold — exact no-op if acc == 0
#pragma unroll
    for (int i = 0; i < 4; i++)
#pragma unroll
        for (int j2 = 0; j2 < 4; j2++) {
            float lo, hi;
            unpack2(acc2[i][j2], lo, hi);
            int e = i * 8 + j2 * 2;
            Csm[e * NTHREADS + tid]       = __fadd_rn(Csm[e * NTHREADS + tid], lo);
            Csm[(e + 1) * NTHREADS + tid] = __fadd_rn(Csm[(e + 1) * NTHREADS + tid], hi);
        }

    if (EPI == 0) {
        float as = act_s[0];
        float bsv[8], bbv[8];
#pragma unroll
        for (int j = 0; j < 8; j++) {
            bsv[j] = bns[bn0 + tn + j];
            bbv[j] = bnb[bn0 + tn + j];
        }
#pragma unroll
        for (int i = 0; i < 4; i++) {
            float pk[8];
#pragma unroll
            for (int j = 0; j < 8; j++) {
                float c   = Csm[(i * 8 + j) * NTHREADS + tid];
                float m   = __fmul_rn(c, bsv[j]);
                float pre = __fadd_rn(m, bbv[j]);
                float t   = __fdiv_rn(fmaxf(pre, 0.0f), as);
                t = fminf(fmaxf(t, 0.0f), 15.0f);
                pk[j] = __fmul_rn(rintf(t), as);
            }
            float4* dst = reinterpret_cast<float4*>(
                outF + (size_t)(bm0 + tm + i) * H_DIM + bn0 + tn);
            dst[0] = *reinterpret_cast<const float4*>(pk);
            dst[1] = *reinterpret_cast<const float4*>(pk + 4);
        }
    } else {
#pragma unroll
        for (int i = 0; i < 4; i++) {
            size_t row = (size_t)(bm0 + tm + i);
#pragma unroll
            for (int j = 0; j < 8; j++) {
                int col = bn0 + tn + j;
                if (col < C_DIM)
                    outF[row * C_DIM + col] = Csm[(i * 8 + j) * NTHREADS + tid];
            }
        }
    }
}

// ---------------- launch --------------------------------------------------
extern "C" void kernel_launch(void* const* d_in, const int* in_sizes, int n_in,
                              void* d_out, int out_size) {
    (void)in_sizes; (void)n_in; (void)out_size;
    const float* x    = (const float*)d_in[0];
    const float* w1   = (const float*)d_in[1];
    const float* w2   = (const float*)d_in[2];
    const float* w3   = (const float*)d_in[3];
    const float* w4   = (const float*)d_in[4];
    const float* bns1 = (const float*)d_in[5];
    const float* bnb1 = (const float*)d_in[6];
    const float* bns2 = (const float*)d_in[7];
    const float* bnb2 = (const float*)d_in[8];
    const float* bns3 = (const float*)d_in[9];
    const float* bnb3 = (const float*)d_in[10];
    const float* as1  = (const float*)d_in[11];
    const float* as2  = (const float*)d_in[12];
    const float* as3  = (const float*)d_in[13];
    float* out = (float*)d_out;

    float *w1q, *w2q, *w3q, *w4q, *h1, *h2;
    cudaGetSymbolAddress((void**)&w1q, g_w1q);
    cudaGetSymbolAddress((void**)&w2q, g_w2q);
    cudaGetSymbolAddress((void**)&w3q, g_w3q);
    cudaGetSymbolAddress((void**)&w4q, g_w4q);
    cudaGetSymbolAddress((void**)&h1,  g_h1);
    cudaGetSymbolAddress((void**)&h2,  g_h2);

    const int SMEM = (2 * BK * 128 + 32 * NTHREADS) * sizeof(float);  // 80 KB
    cudaFuncSetAttribute(k_gemm<0>, cudaFuncAttributeMaxDynamicSharedMemorySize, SMEM);
    cudaFuncSetAttribute(k_gemm<1>, cudaFuncAttributeMaxDynamicSharedMemorySize, SMEM);

    // launches 1-3: prologue; launches 4-7: GEMMs (ncu -s 5 lands on a GEMM)
    k_zero_absmax<<<1, 32>>>();
    k_absmax_all<<<4352, 256>>>(w1, w2, w3, w4);
    k_quant_all<<<8704, 256>>>(w1, w2, w3, w4, w1q, w2q, w3q, w4q);

    dim3 gHH(H_DIM / 128, B_DIM / 128);
    dim3 gC (C_PAD / 128, B_DIM / 128);
    k_gemm<0><<<gHH, NTHREADS, SMEM>>>(x,  w1q, D_DIM, h1,  bns1, bnb1, as1);
    k_gemm<0><<<gHH, NTHREADS, SMEM>>>(h1, w2q, H_DIM, h2,  bns2, bnb2, as2);
    k_gemm<0><<<gHH, NTHREADS, SMEM>>>(h2, w3q, H_DIM, h1,  bns3, bnb3, as3);
    k_gemm<1><<<gC,  NTHREADS, SMEM>>>(h1, w4q, H_DIM, out, nullptr, nullptr, nullptr);
}

// round 13
// speedup vs baseline: 1.5985x; 1.5985x over previous
#include <cuda_runtime.h>
#include <cstdint>
#include <cstddef>

// Problem shape (fixed by setup_inputs)
#define B_DIM 8192
#define D_DIM 4096
#define H_DIM 8192
#define C_DIM 1000
#define C_PAD 1024

// ACL arm_gemm GemmHybrid fp32 K-blocking (verified PASS): KC = 512.
#define KC 512
#define BK 16
#define KC_TILES (KC / BK)   // fold period in BK=16 tiles

typedef unsigned long long u64;

// ---- packed dual-fp32 FMA (sm_100+): per-lane IEEE RN fp32 FMA -------------
__device__ __forceinline__ u64 pack2(float lo, float hi) {
    u64 r;
    asm("mov.b64 %0, {%1, %2};" : "=l"(r) : "f"(lo), "f"(hi));
    return r;
}
__device__ __forceinline__ void unpack2(u64 v, float& lo, float& hi) {
    asm("mov.b64 {%0, %1}, %2;" : "=f"(lo), "=f"(hi) : "l"(v));
}
__device__ __forceinline__ void fma2(u64& d, u64 a, u64 b, u64 c) {
    asm("fma.rn.f32x2 %0, %1, %2, %3;" : "=l"(d) : "l"(a), "l"(b), "l"(c));
}

// ---------------- scratch (static device arrays; no runtime allocation) ----
__device__ float g_w1q[(size_t)H_DIM * D_DIM];   // 128 MB  fl(q*scale) weights
__device__ float g_w2q[(size_t)H_DIM * H_DIM];   // 256 MB
__device__ float g_w3q[(size_t)H_DIM * H_DIM];   // 256 MB
__device__ float g_w4q[(size_t)C_PAD * H_DIM];   //  32 MB (rows 1000..1023 zero)
__device__ float g_h1 [(size_t)B_DIM * H_DIM];   // 256 MB (float activations)
__device__ float g_h2 [(size_t)B_DIM * H_DIM];   // 256 MB
__device__ unsigned g_absmax[4];

// ---------------- prologue: zero + fused absmax + fused quant --------------
__global__ void k_zero_absmax() {
    if (threadIdx.x < 4) g_absmax[threadIdx.x] = 0u;
}

__device__ __forceinline__ void absmax_range(const float* __restrict__ w,
                                             size_t n, int idx,
                                             int rb, int nb) {
    __shared__ unsigned sm[256];
    unsigned m = 0u;
    size_t stride = (size_t)nb * 256;
    for (size_t i = (size_t)rb * 256 + threadIdx.x; i < n; i += stride) {
        unsigned b = __float_as_uint(fabsf(w[i]));  // abs-float bit order == value order
        m = m > b ? m : b;
    }
    sm[threadIdx.x] = m;
    __syncthreads();
    for (int s = 128; s > 0; s >>= 1) {
        if (threadIdx.x < (unsigned)s) {
            unsigned o = sm[threadIdx.x + s];
            if (o > sm[threadIdx.x]) sm[threadIdx.x] = o;
        }
        __syncthreads();
    }
    if (threadIdx.x == 0) atomicMax(&g_absmax[idx], sm[0]);
}

__global__ void __launch_bounds__(256) k_absmax_all(const float* __restrict__ w1,
                                                    const float* __restrict__ w2,
                                                    const float* __restrict__ w3,
                                                    const float* __restrict__ w4) {
    int b = blockIdx.x;
    if (b < 1024)      absmax_range(w1, (size_t)H_DIM * D_DIM, 0, b,        1024);
    else if (b < 2560) absmax_range(w2, (size_t)H_DIM * H_DIM, 1, b - 1024, 1536);
    else if (b < 4096) absmax_range(w3, (size_t)H_DIM * H_DIM, 2, b - 2560, 1536);
    else               absmax_range(w4, (size_t)C_DIM * H_DIM, 3, b - 4096, 256);
}

// fl(round(clip(w/s,-3,3)) * s) — IEEE RN div/mul, rintf = half-even = jnp.round
__device__ __forceinline__ void quant_range(const float* __restrict__ w,
                                            float* __restrict__ q,
                                            size_t n_real, size_t n_total,
                                            int idx, int rb, int nb) {
    float scale = __fdiv_rn(__uint_as_float(g_absmax[idx]), 3.0f);
    size_t stride = (size_t)nb * 256;
    for (size_t i = (size_t)rb * 256 + threadIdx.x; i < n_total; i += stride) {
        float v = 0.0f;
        if (i < n_real) {
            float t = __fdiv_rn(w[i], scale);
            t = fminf(fmaxf(t, -3.0f), 3.0f);
            v = __fmul_rn(rintf(t), scale);
        }
        q[i] = v;
    }
}

__global__ void __launch_bounds__(256) k_quant_all(const float* __restrict__ w1,
                                                   const float* __restrict__ w2,
                                                   const float* __restrict__ w3,
                                                   const float* __restrict__ w4,
                                                   float* q1, float* q2,
                                                   float* q3, float* q4) {
    int b = blockIdx.x;
    size_t n1 = (size_t)H_DIM * D_DIM, n2 = (size_t)H_DIM * H_DIM;
    if (b < 2048)      quant_range(w1, q1, n1, n1, 0, b,        2048);
    else if (b < 5120) quant_range(w2, q2, n2, n2, 1, b - 2048, 3072);
    else if (b < 8192) quant_range(w3, q3, n2, n2, 2, b - 5120, 3072);
    else               quant_range(w4, q4, (size_t)C_DIM * H_DIM,
                                   (size_t)C_PAD * H_DIM, 3, b - 8192, 512);
}

// ---------------- ACL-hybrid-order GEMM, FFMA2 + prefetch, 2 CTA/SM --------
// Numerics contract (verified PASS): per output element, K split into KC=512
// panels; within a panel a serial ascending fp32 FMA chain from 0; panels
// folded sequentially with one fp32 add each. FFMA2 lanes are independent
// per-element chains (pair over adjacent j) — bit-identical to scalar FFMA.
// R10 engine (verified 64.3ms) + __launch_bounds__(256,2): regs<=128 ->
// 2 CTAs/SM -> 4 warps/SMSP to hide LDS/barrier latency at the same
// smem-traffic/FLOP ratio (8x8 per-thread tile).
template <int EPI>
__global__ void __launch_bounds__(256, 2) k_gemm(const float* __restrict__ A,
                                                 const float* __restrict__ Bw,
                                                 int K,
                                                 float* __restrict__ outF,
                                                 const float* __restrict__ bns,
                                                 const float* __restrict__ bnb,
                                                 const float* __restrict__ act_s) {
    extern __shared__ float smdyn[];
    float (*As)[128] = reinterpret_cast<float(*)[128]>(smdyn);              // [BK][128]
    float (*Bs)[128] = reinterpret_cast<float(*)[128]>(smdyn + BK * 128);   // [BK][128]
    float* Csm       = smdyn + 2 * BK * 128;                                // [64][256]

    int bn0 = blockIdx.x * 128;
    int bm0 = blockIdx.y * 128;
    int tid = threadIdx.x;
    int tm = (tid >> 4) << 3;   // 0,8,..,120
    int tn = (tid & 15) << 3;

    u64 acc2[8][4];             // acc2[i][j2] = (acc[i][2j2], acc[i][2j2+1])
#pragma unroll
    for (int i = 0; i < 8; i++)
#pragma unroll
        for (int j2 = 0; j2 < 4; j2++) acc2[i][j2] = 0ull;
#pragma unroll
    for (int e = 0; e < 64; e++) Csm[e * 256 + tid] = 0.0f;

    int lr = tid >> 1;          // 0..127 (row within tile)
    int lc = (tid & 1) * 8;     // 0 or 8 (col within BK=16 K slab)

    const float4* ga = reinterpret_cast<const float4*>(
        A + (size_t)(bm0 + lr) * K + lc);
    const float4* gb = reinterpret_cast<const float4*>(
        Bw + (size_t)(bn0 + lr) * K + lc);

    // ---- load tile 0 ----
    float4 pa0 = ga[0], pa1 = ga[1];
    float4 pb0 = gb[0], pb1 = gb[1];

    int nt = K / BK;
    for (int t = 0; t < nt; t++) {
        // store current tile to smem
        As[lc + 0][lr] = pa0.x; As[lc + 1][lr] = pa0.y;
        As[lc + 2][lr] = pa0.z; As[lc + 3][lr] = pa0.w;
        As[lc + 4][lr] = pa1.x; As[lc + 5][lr] = pa1.y;
        As[lc + 6][lr] = pa1.z; As[lc + 7][lr] = pa1.w;
        Bs[lc + 0][lr] = pb0.x; Bs[lc + 1][lr] = pb0.y;
        Bs[lc + 2][lr] = pb0.z; Bs[lc + 3][lr] = pb0.w;
        Bs[lc + 4][lr] = pb1.x; Bs[lc + 5][lr] = pb1.y;
        Bs[lc + 6][lr] = pb1.z; Bs[lc + 7][lr] = pb1.w;
        __syncthreads();

        // prefetch next tile into registers (hides DRAM/L2 latency)
        if (t + 1 < nt) {
            const float4* na = ga + (size_t)(t + 1) * (BK >> 2);
            const float4* nb = gb + (size_t)(t + 1) * (BK >> 2);
            pa0 = na[0]; pa1 = na[1];
            pb0 = nb[0]; pb1 = nb[1];
        }

#pragma unroll
        for (int k = 0; k < BK; k++) {   // ascending k: serial dependent FMA chain
            float a[8], b[8];
            *reinterpret_cast<float4*>(a)     = *reinterpret_cast<const float4*>(&As[k][tm]);
            *reinterpret_cast<float4*>(a + 4) = *reinterpret_cast<const float4*>(&As[k][tm + 4]);
            *reinterpret_cast<float4*>(b)     = *reinterpret_cast<const float4*>(&Bs[k][tn]);
            *reinterpret_cast<float4*>(b + 4) = *reinterpret_cast<const float4*>(&Bs[k][tn + 4]);
            // b pairs: adjacent registers of the aligned v4 quads — no packing
            u64 b2[4];
            b2[0] = *reinterpret_cast<const u64*>(&b[0]);
            b2[1] = *reinterpret_cast<const u64*>(&b[2]);
            b2[2] = *reinterpret_cast<const u64*>(&b[4]);
            b2[3] = *reinterpret_cast<const u64*>(&b[6]);
#pragma unroll
            for (int i = 0; i < 8; i++) {
                u64 a2 = pack2(a[i], a[i]);
#pragma unroll
                for (int j2 = 0; j2 < 4; j2++)
                    fma2(acc2[i][j2], a2, b2[j2], acc2[i][j2]);
            }
        }
        __syncthreads();
        if (((t + 1) % KC_TILES) == 0) {   // panel boundary: fold partial into C
#pragma unroll
            for (int i = 0; i < 8; i++)
#pragma unroll
                for (int j2 = 0; j2 < 4; j2++) {
                    float lo, hi;
                    unpack2(acc2[i][j2], lo, hi);
                    int e = i * 8 + j2 * 2;
                    Csm[e * 256 + tid]       = __fadd_rn(Csm[e * 256 + tid], lo);
                    Csm[(e + 1) * 256 + tid] = __fadd_rn(Csm[(e + 1) * 256 + tid], hi);
                    acc2[i][j2] = 0ull;
                }
        }
    }
    // final (possibly partial) panel fold — exact no-op if acc == 0
#pragma unroll
    for (int i = 0; i < 8; i++)
#pragma unroll
        for (int j2 = 0; j2 < 4; j2++) {
            float lo, hi;
            unpack2(acc2[i][j2], lo, hi);
            int e = i * 8 + j2 * 2;
            Csm[e * 256 + tid]       = __fadd_rn(Csm[e * 256 + tid], lo);
            Csm[(e + 1) * 256 + tid] = __fadd_rn(Csm[(e + 1) * 256 + tid], hi);
        }

    if (EPI == 0) {
        float as = act_s[0];
        float bsv[8], bbv[8];
#pragma unroll
        for (int j = 0; j < 8; j++) {
            bsv[j] = bns[bn0 + tn + j];
            bbv[j] = bnb[bn0 + tn + j];
        }
#pragma unroll
        for (int i = 0; i < 8; i++) {
            float pk[8];
#pragma unroll
            for (int j = 0; j < 8; j++) {
                float c   = Csm[(i * 8 + j) * 256 + tid];
                float m   = __fmul_rn(c, bsv[j]);
                float pre = __fadd_rn(m, bbv[j]);
                float t   = __fdiv_rn(fmaxf(pre, 0.0f), as);
                t = fminf(fmaxf(t, 0.0f), 15.0f);
                pk[j] = __fmul_rn(rintf(t), as);
            }
            float4* dst = reinterpret_cast<float4*>(
                outF + (size_t)(bm0 + tm + i) * H_DIM + bn0 + tn);
            dst[0] = *reinterpret_cast<const float4*>(pk);
            dst[1] = *reinterpret_cast<const float4*>(pk + 4);
        }
    } else {
#pragma unroll
        for (int i = 0; i < 8; i++) {
            size_t row = (size_t)(bm0 + tm + i);
#pragma unroll
            for (int j = 0; j < 8; j++) {
                int col = bn0 + tn + j;
                if (col < C_DIM) outF[row * C_DIM + col] = Csm[(i * 8 + j) * 256 + tid];
            }
        }
    }
}

// ---------------- launch --------------------------------------------------
extern "C" void kernel_launch(void* const* d_in, const int* in_sizes, int n_in,
                              void* d_out, int out_size) {
    (void)in_sizes; (void)n_in; (void)out_size;
    const float* x    = (const float*)d_in[0];
    const float* w1   = (const float*)d_in[1];
    const float* w2   = (const float*)d_in[2];
    const float* w3   = (const float*)d_in[3];
    const float* w4   = (const float*)d_in[4];
    const float* bns1 = (const float*)d_in[5];
    const float* bnb1 = (const float*)d_in[6];
    const float* bns2 = (const float*)d_in[7];
    const float* bnb2 = (const float*)d_in[8];
    const float* bns3 = (const float*)d_in[9];
    const float* bnb3 = (const float*)d_in[10];
    const float* as1  = (const float*)d_in[11];
    const float* as2  = (const float*)d_in[12];
    const float* as3  = (const float*)d_in[13];
    float* out = (float*)d_out;

    float *w1q, *w2q, *w3q, *w4q, *h1, *h2;
    cudaGetSymbolAddress((void**)&w1q, g_w1q);
    cudaGetSymbolAddress((void**)&w2q, g_w2q);
    cudaGetSymbolAddress((void**)&w3q, g_w3q);
    cudaGetSymbolAddress((void**)&w4q, g_w4q);
    cudaGetSymbolAddress((void**)&h1,  g_h1);
    cudaGetSymbolAddress((void**)&h2,  g_h2);

    const int SMEM = (2 * BK * 128 + 64 * 256) * sizeof(float);  // 80 KB
    cudaFuncSetAttribute(k_gemm<0>, cudaFuncAttributeMaxDynamicSharedMemorySize, SMEM);
    cudaFuncSetAttribute(k_gemm<1>, cudaFuncAttributeMaxDynamicSharedMemorySize, SMEM);

    // launches 1-3: prologue; launches 4-7: GEMMs (ncu -s 5 lands on a GEMM)
    k_zero_absmax<<<1, 32>>>();
    k_absmax_all<<<4352, 256>>>(w1, w2, w3, w4);
    k_quant_all<<<8704, 256>>>(w1, w2, w3, w4, w1q, w2q, w3q, w4q);

    dim3 gHH(H_DIM / 128, B_DIM / 128);
    dim3 gC (C_PAD / 128, B_DIM / 128);
    k_gemm<0><<<gHH, 256, SMEM>>>(x,  w1q, D_DIM, h1,  bns1, bnb1, as1);
    k_gemm<0><<<gHH, 256, SMEM>>>(h1, w2q, H_DIM, h2,  bns2, bnb2, as2);
    k_gemm<0><<<gHH, 256, SMEM>>>(h2, w3q, H_DIM, h1,  bns3, bnb3, as3);
    k_gemm<1><<<gC,  256, SMEM>>>(h1, w4q, H_DIM, out, nullptr, nullptr, nullptr);
}

// round 14
// speedup vs baseline: 2.0321x; 1.2712x over previous
#include <cuda_runtime.h>
#include <cstdint>
#include <cstddef>

// Problem shape (fixed by setup_inputs)
#define B_DIM 8192
#define D_DIM 4096
#define H_DIM 8192
#define C_DIM 1000
#define C_PAD 1024

// ACL arm_gemm GemmHybrid fp32 K-blocking (verified PASS): KC = 512.
#define KC 512
#define BK 16
#define KC_TILES (KC / BK)   // fold period in BK=16 tiles
#define BROW 192             // Bs floats per k-row: 16 groups x 12 (48B stride)

typedef unsigned long long u64;

// ---- packed dual-fp32 FMA (sm_100+): per-lane IEEE RN fp32 FMA -------------
__device__ __forceinline__ u64 pack2(float lo, float hi) {
    u64 r;
    asm("mov.b64 %0, {%1, %2};" : "=l"(r) : "f"(lo), "f"(hi));
    return r;
}
__device__ __forceinline__ void unpack2(u64 v, float& lo, float& hi) {
    asm("mov.b64 {%0, %1}, %2;" : "=f"(lo), "=f"(hi) : "l"(v));
}
__device__ __forceinline__ void fma2(u64& d, u64 a, u64 b, u64 c) {
    asm("fma.rn.f32x2 %0, %1, %2, %3;" : "=l"(d) : "l"(a), "l"(b), "l"(c));
}

// ---------------- scratch (static device arrays; no runtime allocation) ----
__device__ float  g_w1q[(size_t)H_DIM * D_DIM];   // 128 MB fl(q*scale) weights
__device__ float  g_w2q[(size_t)H_DIM * H_DIM];   // 256 MB
__device__ float  g_w3q[(size_t)H_DIM * H_DIM];   // 256 MB
__device__ int8_t g_q4i[(size_t)C_PAD * H_DIM];   //   8 MB int q (padded rows 0)
__device__ float  g_h1 [(size_t)B_DIM * H_DIM];   // 256 MB float activations
__device__ float  g_h2 [(size_t)B_DIM * H_DIM];   // 256 MB
__device__ int8_t g_h3i[(size_t)B_DIM * H_DIM];   //  64 MB int codes (layer 3)
__device__ unsigned g_absmax[4];

// ---------------- prologue: zero + fused absmax + quant ---------------------
__global__ void k_zero_absmax() {
    if (threadIdx.x < 4) g_absmax[threadIdx.x] = 0u;
}

__device__ __forceinline__ void absmax_range(const float* __restrict__ w,
                                             size_t n, int idx,
                                             int rb, int nb) {
    __shared__ unsigned sm[256];
    unsigned m = 0u;
    size_t stride = (size_t)nb * 256;
    for (size_t i = (size_t)rb * 256 + threadIdx.x; i < n; i += stride) {
        unsigned b = __float_as_uint(fabsf(w[i]));  // abs-float bit order == value order
        m = m > b ? m : b;
    }
    sm[threadIdx.x] = m;
    __syncthreads();
    for (int s = 128; s > 0; s >>= 1) {
        if (threadIdx.x < (unsigned)s) {
            unsigned o = sm[threadIdx.x + s];
            if (o > sm[threadIdx.x]) sm[threadIdx.x] = o;
        }
        __syncthreads();
    }
    if (threadIdx.x == 0) atomicMax(&g_absmax[idx], sm[0]);
}

__global__ void __launch_bounds__(256) k_absmax_all(const float* __restrict__ w1,
                                                    const float* __restrict__ w2,
                                                    const float* __restrict__ w3,
                                                    const float* __restrict__ w4) {
    int b = blockIdx.x;
    if (b < 1024)      absmax_range(w1, (size_t)H_DIM * D_DIM, 0, b,        1024);
    else if (b < 2560) absmax_range(w2, (size_t)H_DIM * H_DIM, 1, b - 1024, 1536);
    else if (b < 4096) absmax_range(w3, (size_t)H_DIM * H_DIM, 2, b - 2560, 1536);
    else               absmax_range(w4, (size_t)C_DIM * H_DIM, 3, b - 4096, 256);
}

// fl(round(clip(w/s,-3,3)) * s) — IEEE RN div/mul, rintf = half-even = jnp.round
__device__ __forceinline__ void quant_range(const float* __restrict__ w,
                                            float* __restrict__ q,
                                            size_t n, int idx, int rb, int nb) {
    float scale = __fdiv_rn(__uint_as_float(g_absmax[idx]), 3.0f);
    size_t stride = (size_t)nb * 256;
    for (size_t i = (size_t)rb * 256 + threadIdx.x; i < n; i += stride) {
        float t = __fdiv_rn(w[i], scale);
        t = fminf(fmaxf(t, -3.0f), 3.0f);
        q[i] = __fmul_rn(rintf(t), scale);
    }
}

__global__ void __launch_bounds__(256) k_quant_all(const float* __restrict__ w1,
                                                   const float* __restrict__ w2,
                                                   const float* __restrict__ w3,
                                                   float* q1, float* q2, float* q3) {
    int b = blockIdx.x;
    size_t n1 = (size_t)H_DIM * D_DIM, n2 = (size_t)H_DIM * H_DIM;
    if (b < 2048)      quant_range(w1, q1, n1, 0, b,        2048);
    else if (b < 5120) quant_range(w2, q2, n2, 1, b - 2048, 3072);
    else               quant_range(w3, q3, n2, 2, b - 5120, 3072);
}

// w4 -> int codes {-3..3} (GEMM4 is tolerance-bound, not bit-exact)
__global__ void __launch_bounds__(256) k_quant4i(const float* __restrict__ w4,
                                                 int8_t* __restrict__ q4) {
    float scale = __fdiv_rn(__uint_as_float(g_absmax[3]), 3.0f);
    size_t n_real = (size_t)C_DIM * H_DIM, n_total = (size_t)C_PAD * H_DIM;
    size_t stride = (size_t)gridDim.x * 256;
    for (size_t i = (size_t)blockIdx.x * 256 + threadIdx.x; i < n_total; i += stride) {
        int8_t v = 0;
        if (i < n_real) {
            float t = __fdiv_rn(w4[i], scale);
            t = fminf(fmaxf(t, -3.0f), 3.0f);
            v = (int8_t)(int)rintf(t);
        }
        q4[i] = v;
    }
}

// ---------------- ACL-hybrid-order GEMM, FFMA2 + prefetch, 2 CTA/SM --------
// Numerics contract (verified PASS): per output element, K split into KC=512
// panels; within a panel a serial ascending fp32 FMA chain from 0; panels
// folded sequentially with one fp32 add each. FFMA2 lanes are independent
// per-element chains (pair over adjacent j) — bit-identical to scalar FFMA.
// Bs uses a 48B group stride (16 groups x 12 floats) so the 16 lane chunks
// cover all 32 banks -> 2 crossbar cycles per LDS.128 instead of 4.
// EPI 0: quant_relu((C*bns+bnb)) -> float h (stride H_DIM)
// EPI 2: quant_relu -> int8 codes 0..15 (stride H_DIM) for dp4a GEMM4
template <int EPI>
__global__ void __launch_bounds__(256, 2) k_gemm(const float* __restrict__ A,
                                                 const float* __restrict__ Bw,
                                                 int K,
                                                 float* __restrict__ outF,
                                                 int8_t* __restrict__ out8,
                                                 const float* __restrict__ bns,
                                                 const float* __restrict__ bnb,
                                                 const float* __restrict__ act_s) {
    extern __shared__ float smdyn[];
    float (*As)[128] = reinterpret_cast<float(*)[128]>(smdyn);             // [BK][128]
    float* Bs        = smdyn + BK * 128;                                    // [BK][BROW]
    float* Csm       = smdyn + BK * 128 + BK * BROW;                        // [64][256]

    int bn0 = blockIdx.x * 128;
    int bm0 = blockIdx.y * 128;
    int tid = threadIdx.x;
    int tm = (tid >> 4) << 3;   // 0,8,..,120
    int tn = (tid & 15) << 3;

    u64 acc2[8][4];             // acc2[i][j2] = (acc[i][2j2], acc[i][2j2+1])
#pragma unroll
    for (int i = 0; i < 8; i++)
#pragma unroll
        for (int j2 = 0; j2 < 4; j2++) acc2[i][j2] = 0ull;
#pragma unroll
    for (int e = 0; e < 64; e++) Csm[e * 256 + tid] = 0.0f;

    int lr = tid >> 1;          // 0..127 (row within tile)
    int lc = (tid & 1) * 8;     // 0 or 8 (col within BK=16 K slab)
    int bgrp = (lr >> 3) * 12 + (lr & 7);   // Bs position for n-row lr

    const float4* ga = reinterpret_cast<const float4*>(
        A + (size_t)(bm0 + lr) * K + lc);
    const float4* gb = reinterpret_cast<const float4*>(
        Bw + (size_t)(bn0 + lr) * K + lc);

    // ---- load tile 0 ----
    float4 pa0 = ga[0], pa1 = ga[1];
    float4 pb0 = gb[0], pb1 = gb[1];

    int nt = K / BK;
    for (int t = 0; t < nt; t++) {
        // store current tile to smem
        As[lc + 0][lr] = pa0.x; As[lc + 1][lr] = pa0.y;
        As[lc + 2][lr] = pa0.z; As[lc + 3][lr] = pa0.w;
        As[lc + 4][lr] = pa1.x; As[lc + 5][lr] = pa1.y;
        As[lc + 6][lr] = pa1.z; As[lc + 7][lr] = pa1.w;
        Bs[(lc + 0) * BROW + bgrp] = pb0.x; Bs[(lc + 1) * BROW + bgrp] = pb0.y;
        Bs[(lc + 2) * BROW + bgrp] = pb0.z; Bs[(lc + 3) * BROW + bgrp] = pb0.w;
        Bs[(lc + 4) * BROW + bgrp] = pb1.x; Bs[(lc + 5) * BROW + bgrp] = pb1.y;
        Bs[(lc + 6) * BROW + bgrp] = pb1.z; Bs[(lc + 7) * BROW + bgrp] = pb1.w;
        __syncthreads();

        // prefetch next tile into registers (hides DRAM/L2 latency)
        if (t + 1 < nt) {
            const float4* na = ga + (size_t)(t + 1) * (BK >> 2);
            const float4* nb = gb + (size_t)(t + 1) * (BK >> 2);
            pa0 = na[0]; pa1 = na[1];
            pb0 = nb[0]; pb1 = nb[1];
        }

#pragma unroll
        for (int k = 0; k < BK; k++) {   // ascending k: serial dependent FMA chain
            float a[8], b[8];
            *reinterpret_cast<float4*>(a)     = *reinterpret_cast<const float4*>(&As[k][tm]);
            *reinterpret_cast<float4*>(a + 4) = *reinterpret_cast<const float4*>(&As[k][tm + 4]);
            const float* brow = &Bs[k * BROW + (tid & 15) * 12];
            *reinterpret_cast<float4*>(b)     = *reinterpret_cast<const float4*>(brow);
            *reinterpret_cast<float4*>(b + 4) = *reinterpret_cast<const float4*>(brow + 4);
            // b pairs: adjacent registers of the aligned v4 quads — no packing
            u64 b2[4];
            b2[0] = *reinterpret_cast<const u64*>(&b[0]);
            b2[1] = *reinterpret_cast<const u64*>(&b[2]);
            b2[2] = *reinterpret_cast<const u64*>(&b[4]);
            b2[3] = *reinterpret_cast<const u64*>(&b[6]);
#pragma unroll
            for (int i = 0; i < 8; i++) {
                u64 a2 = pack2(a[i], a[i]);
#pragma unroll
                for (int j2 = 0; j2 < 4; j2++)
                    fma2(acc2[i][j2], a2, b2[j2], acc2[i][j2]);
            }
        }
        __syncthreads();
        if (((t + 1) % KC_TILES) == 0) {   // panel boundary: fold partial into C
#pragma unroll
            for (int i = 0; i < 8; i++)
#pragma unroll
                for (int j2 = 0; j2 < 4; j2++) {
                    float lo, hi;
                    unpack2(acc2[i][j2], lo, hi);
                    int e = i * 8 + j2 * 2;
                    Csm[e * 256 + tid]       = __fadd_rn(Csm[e * 256 + tid], lo);
                    Csm[(e + 1) * 256 + tid] = __fadd_rn(Csm[(e + 1) * 256 + tid], hi);
                    acc2[i][j2] = 0ull;
                }
        }
    }
    // final (possibly partial) panel fold — exact no-op if acc == 0
#pragma unroll
    for (int i = 0; i < 8; i++)
#pragma unroll
        for (int j2 = 0; j2 < 4; j2++) {
            float lo, hi;
            unpack2(acc2[i][j2], lo, hi);
            int e = i * 8 + j2 * 2;
            Csm[e * 256 + tid]       = __fadd_rn(Csm[e * 256 + tid], lo);
            Csm[(e + 1) * 256 + tid] = __fadd_rn(Csm[(e + 1) * 256 + tid], hi);
        }

    float as = act_s[0];
    float bsv[8], bbv[8];
#pragma unroll
    for (int j = 0; j < 8; j++) {
        bsv[j] = bns[bn0 + tn + j];
        bbv[j] = bnb[bn0 + tn + j];
    }
    if (EPI == 0) {
#pragma unroll
        for (int i = 0; i < 8; i++) {
            float pk[8];
#pragma unroll
            for (int j = 0; j < 8; j++) {
                float c   = Csm[(i * 8 + j) * 256 + tid];
                float m   = __fmul_rn(c, bsv[j]);
                float pre = __fadd_rn(m, bbv[j]);
                float t   = __fdiv_rn(fmaxf(pre, 0.0f), as);
                t = fminf(fmaxf(t, 0.0f), 15.0f);
                pk[j] = __fmul_rn(rintf(t), as);
            }
            float4* dst = reinterpret_cast<float4*>(
                outF + (size_t)(bm0 + tm + i) * H_DIM + bn0 + tn);
            dst[0] = *reinterpret_cast<const float4*>(pk);
            dst[1] = *reinterpret_cast<const float4*>(pk + 4);
        }
    } else {   // EPI == 2: int8 codes for dp4a GEMM4
#pragma unroll
        for (int i = 0; i < 8; i++) {
            char pk[8];
#pragma unroll
            for (int j = 0; j < 8; j++) {
                float c   = Csm[(i * 8 + j) * 256 + tid];
                float m   = __fmul_rn(c, bsv[j]);
                float pre = __fadd_rn(m, bbv[j]);
                float t   = __fdiv_rn(fmaxf(pre, 0.0f), as);
                t = fminf(fmaxf(t, 0.0f), 15.0f);
                pk[j] = (char)(int)rintf(t);
            }
            *reinterpret_cast<int2*>(out8 + (size_t)(bm0 + tm + i) * H_DIM + bn0 + tn) =
                *reinterpret_cast<const int2*>(pk);
        }
    }
}

// ---------------- GEMM 4: exact-int dp4a (tolerance-bound output) ----------
__global__ void __launch_bounds__(256) k_gemm4(const float* __restrict__ act_prev,
                                               float* __restrict__ out) {
    const int BKW = 16;
    __shared__ int As[BKW][128];
    __shared__ int Bs[BKW][128];

    const int8_t* Ain = g_h3i;
    const int8_t* W   = g_q4i;

    int bn0 = blockIdx.x * 128;
    int bm0 = blockIdx.y * 128;
    int tid = threadIdx.x;
    int tm = (tid >> 4) << 3;
    int tn = (tid & 15) << 3;

    int acc[8][8];
#pragma unroll
    for (int i = 0; i < 8; i++)
#pragma unroll
        for (int j = 0; j < 8; j++) acc[i][j] = 0;

    int lr = tid >> 1;
    int lq = (tid & 1) * 8;

    for (int k0 = 0; k0 < H_DIM; k0 += 64) {
        {
            const int4* src = reinterpret_cast<const int4*>(
                Ain + (size_t)(bm0 + lr) * H_DIM + k0 + lq * 4);
            int4 v0 = src[0], v1 = src[1];
            As[lq + 0][lr] = v0.x; As[lq + 1][lr] = v0.y;
            As[lq + 2][lr] = v0.z; As[lq + 3][lr] = v0.w;
            As[lq + 4][lr] = v1.x; As[lq + 5][lr] = v1.y;
            As[lq + 6][lr] = v1.z; As[lq + 7][lr] = v1.w;
        }
        {
            const int4* src = reinterpret_cast<const int4*>(
                W + (size_t)(bn0 + lr) * H_DIM + k0 + lq * 4);
            int4 v0 = src[0], v1 = src[1];
            Bs[lq + 0][lr] = v0.x; Bs[lq + 1][lr] = v0.y;
            Bs[lq + 2][lr] = v0.z; Bs[lq + 3][lr] = v0.w;
            Bs[lq + 4][lr] = v1.x; Bs[lq + 5][lr] = v1.y;
            Bs[lq + 6][lr] = v1.z; Bs[lq + 7][lr] = v1.w;
        }
        __syncthreads();
#pragma unroll
        for (int kw = 0; kw < BKW; kw++) {
            int a[8], b[8];
            *reinterpret_cast<int4*>(a)     = *reinterpret_cast<const int4*>(&As[kw][tm]);
            *reinterpret_cast<int4*>(a + 4) = *reinterpret_cast<const int4*>(&As[kw][tm + 4]);
            *reinterpret_cast<int4*>(b)     = *reinterpret_cast<const int4*>(&Bs[kw][tn]);
            *reinterpret_cast<int4*>(b + 4) = *reinterpret_cast<const int4*>(&Bs[kw][tn + 4]);
#pragma unroll
            for (int i = 0; i < 8; i++)
#pragma unroll
                for (int j = 0; j < 8; j++) acc[i][j] = __dp4a(a[i], b[j], acc[i][j]);
        }
        __syncthreads();
    }

    float s4 = __fdiv_rn(__uint_as_float(g_absmax[3]), 3.0f);
    float sc = s4 * act_prev[0];
#pragma unroll
    for (int i = 0; i < 8; i++) {
        size_t row = (size_t)(bm0 + tm + i);
#pragma unroll
        for (int j = 0; j < 8; j++) {
            int col = bn0 + tn + j;
            if (col < C_DIM) out[row * C_DIM + col] = (float)acc[i][j] * sc;
        }
    }
}

// ---------------- launch --------------------------------------------------
extern "C" void kernel_launch(void* const* d_in, const int* in_sizes, int n_in,
                              void* d_out, int out_size) {
    (void)in_sizes; (void)n_in; (void)out_size;
    const float* x    = (const float*)d_in[0];
    const float* w1   = (const float*)d_in[1];
    const float* w2   = (const float*)d_in[2];
    const float* w3   = (const float*)d_in[3];
    const float* w4   = (const float*)d_in[4];
    const float* bns1 = (const float*)d_in[5];
    const float* bnb1 = (const float*)d_in[6];
    const float* bns2 = (const float*)d_in[7];
    const float* bnb2 = (const float*)d_in[8];
    const float* bns3 = (const float*)d_in[9];
    const float* bnb3 = (const float*)d_in[10];
    const float* as1  = (const float*)d_in[11];
    const float* as2  = (const float*)d_in[12];
    const float* as3  = (const float*)d_in[13];
    float* out = (float*)d_out;

    float *w1q, *w2q, *w3q, *h1, *h2;
    int8_t *q4i, *h3i;
    cudaGetSymbolAddress((void**)&w1q, g_w1q);
    cudaGetSymbolAddress((void**)&w2q, g_w2q);
    cudaGetSymbolAddress((void**)&w3q, g_w3q);
    cudaGetSymbolAddress((void**)&q4i, g_q4i);
    cudaGetSymbolAddress((void**)&h1,  g_h1);
    cudaGetSymbolAddress((void**)&h2,  g_h2);
    cudaGetSymbolAddress((void**)&h3i, g_h3i);

    const int SMEM = (BK * 128 + BK * BROW + 64 * 256) * sizeof(float);  // 84 KB
    cudaFuncSetAttribute(k_gemm<0>, cudaFuncAttributeMaxDynamicSharedMemorySize, SMEM);
    cudaFuncSetAttribute(k_gemm<2>, cudaFuncAttributeMaxDynamicSharedMemorySize, SMEM);

    k_zero_absmax<<<1, 32>>>();
    k_absmax_all<<<4352, 256>>>(w1, w2, w3, w4);
    k_quant_all<<<8192, 256>>>(w1, w2, w3, w1q, w2q, w3q);
    k_quant4i<<<512, 256>>>(w4, q4i);

    dim3 gHH(H_DIM / 128, B_DIM / 128);
    dim3 gC (C_PAD / 128, B_DIM / 128);
    k_gemm<0><<<gHH, 256, SMEM>>>(x,  w1q, D_DIM, h1, nullptr, bns1, bnb1, as1);
    k_gemm<0><<<gHH, 256, SMEM>>>(h1, w2q, H_DIM, h2, nullptr, bns2, bnb2, as2);
    k_gemm<2><<<gHH, 256, SMEM>>>(h2, w3q, H_DIM, nullptr, h3i, bns3, bnb3, as3);
    k_gemm4<<<gC, 256>>>(as3, out);
}